// round 15
// baseline (speedup 1.0000x reference)
#include <cuda_runtime.h>
#include <math.h>
#include <stdint.h>

#define BB 4
#define NN 50000
#define KK 128
#define GD 128
#define TPB 128
#define PPC 256                    // points per CTA: 4 warps x 4 mtiles x 16
#define NBLK 196                   // 196*256 = 50176 >= 50000
#define TOTAL_BLK (BB * NBLK)      // 784  (single wave at 6 CTAs/SM: <= 888)
#define MT 4                       // m-tiles per warp

// g_P4: B operand, float4 {P[n=g][k], P[n=g][k+4], P[n=g+8][k], P[n=g+8][k+4]}
//   laid out [b][k8(16)][g(8)][tg(4)]  (k = k8*8 + tg)
//   n: 0-8 = Rrel row-major, 9-11 = u (= ct - Rrel*c), 12 = 1, 13-15 = 0
// g_A4: exp-arg params [b][k8(16)][j(3)][tg(4)] float4:
//   j0 = {ex_k, ex_k+4, ey_k, ey_k+4}, j1 = {ez_k, ez_k+4, a_k, a_k+4}, j2 = {f_k, f_k+4, 0, 0}
__device__ float4 g_P4[BB * 16 * 8 * 4];
__device__ float4 g_A4[BB * 16 * 3 * 4];

__device__ float        g_partial[TOTAL_BLK];
__device__ unsigned int g_count = 0;

__device__ __forceinline__ float ex2f(float x) {
    float y; asm("ex2.approx.ftz.f32 %0, %1;" : "=f"(y) : "f"(x)); return y;
}
__device__ __forceinline__ float tf32r(float x) {
    float y; asm("cvt.rna.tf32.f32 %0, %1;" : "=f"(y) : "f"(x)); return y;
}

__device__ __forceinline__ void mma_tf32(float* c, float a0, float a1,
                                         float a2, float a3,
                                         float b0, float b1) {
    asm("mma.sync.aligned.m16n8k8.row.col.f32.tf32.tf32.f32 "
        "{%0,%1,%2,%3}, {%4,%5,%6,%7}, {%8,%9}, {%0,%1,%2,%3};"
        : "+f"(c[0]), "+f"(c[1]), "+f"(c[2]), "+f"(c[3])
        : "r"(__float_as_uint(a0)), "r"(__float_as_uint(a1)),
          "r"(__float_as_uint(a2)), "r"(__float_as_uint(a3)),
          "r"(__float_as_uint(b0)), "r"(__float_as_uint(b1)));
}

__global__ void precompute_kernel(const float* __restrict__ constants,
                                  const float* __restrict__ scales,
                                  const float* __restrict__ rot,
                                  const float* __restrict__ centers) {
    int idx = blockIdx.x * blockDim.x + threadIdx.x;
    if (idx >= BB * KK) return;
    int b = idx / KK;
    int k = idx - b * KK;
    int bt = (b + 1) & 3;

    const float* R  = rot + (size_t)(b  * KK + k) * 9;
    const float* Rt = rot + (size_t)(bt * KK + k) * 9;
    float Rr[9];
#pragma unroll
    for (int i = 0; i < 3; i++)
#pragma unroll
        for (int l = 0; l < 3; l++)
            Rr[i*3+l] = Rt[i*3+0]*R[l*3+0] + Rt[i*3+1]*R[l*3+1] + Rt[i*3+2]*R[l*3+2];
    const float* c  = centers + (size_t)(b  * KK + k) * 3;
    const float* ct = centers + (size_t)(bt * KK + k) * 3;
    float cx = c[0], cy = c[1], cz = c[2];
    float s  = scales[b * KK + k];
    float cc = constants[b * KK + k];
    float a  = -1.4426950408889634f / (2.0f * s * s);
    float lb = log2f(cc * cc);

    int k8 = k >> 3, j = k & 7, tg = j & 3, half = j >> 2;

    float v[16];
#pragma unroll
    for (int n = 0; n < 9; n++) v[n] = tf32r(Rr[n]);
    v[ 9] = tf32r(ct[0] - (Rr[0]*cx + Rr[1]*cy + Rr[2]*cz));
    v[10] = tf32r(ct[1] - (Rr[3]*cx + Rr[4]*cy + Rr[5]*cz));
    v[11] = tf32r(ct[2] - (Rr[6]*cx + Rr[7]*cy + Rr[8]*cz));
    v[12] = 1.0f; v[13] = 0.0f; v[14] = 0.0f; v[15] = 0.0f;

    float* P4 = (float*)g_P4;
#pragma unroll
    for (int n = 0; n < 16; n++) {
        int g8 = n & 7, hi = n >> 3;
        P4[((((b*16 + k8)*8 + g8)*4 + tg) << 2) + hi*2 + half] = v[n];
    }

    float* A4 = (float*)g_A4;
    float ex = -2.0f * a * cx;
    float ey = -2.0f * a * cy;
    float ez = -2.0f * a * cz;
    float ff = a * (cx*cx + cy*cy + cz*cz) + lb;
    int abase = ((b*16 + k8)*3) * 16 + tg * 4;
    A4[abase +  0 + half]     = ex;
    A4[abase +  0 + 2 + half] = ey;
    A4[abase + 16 + half]     = ez;
    A4[abase + 16 + 2 + half] = a;
    A4[abase + 32 + half]     = ff;
    // comps 2,3 of j2 stay zero-initialized
}

#define UNION_BYTES (PPC * 17 * 4)   // 17408 > 8192 + 3072

__global__ __launch_bounds__(TPB, 6)
void fused_kernel(const float* __restrict__ samples,
                  const float* __restrict__ grid,
                  const float* __restrict__ w2g,
                  float* __restrict__ out) {
    int b   = blockIdx.x / NBLK;
    int blk = blockIdx.x - b * NBLK;
    int bt  = (b + 1) & 3;
    int base = blk * PPC;

    // union: [mainloop] sP4 (8KB) + sA4 (3KB)  /  [epilogue] Cst (17.4KB)
    __shared__ __align__(16) char smem_u[UNION_BYTES];
    __shared__ float  pxs[PPC], pys[PPC], pzs[PPC], sps[PPC];  // 4 KB
    __shared__ float  red[TPB];
    __shared__ bool   s_last;

    float4* sP4 = (float4*)smem_u;               // 512 float4
    float4* sA4 = (float4*)(smem_u + 8192);      // 192 float4
    float*  Cst = (float*)smem_u;                // PPC*17 floats (after sync)

    int tid  = threadIdx.x;
    int lane = tid & 31, warp = tid >> 5;
    int g    = lane >> 2, tg = lane & 3;
    int wbase = warp * 64;

    // ---- stage params + points ----
    {
        const float4* Pg = g_P4 + (size_t)b * 512;
        for (int i = tid; i < 512; i += TPB) sP4[i] = Pg[i];
        const float4* Ag = g_A4 + (size_t)b * 192;
        for (int i = tid; i < 192; i += TPB) sA4[i] = Ag[i];

#pragma unroll
        for (int t = 0; t < 2; t++) {
            int slot = tid + t * TPB;
            int gi = base + slot;
            float px = 0.f, py = 0.f, pz = 0.f;
            if (gi < NN) {
                const float* s6 = samples + (size_t)(b * NN + gi) * 6;
                px = s6[0]; py = s6[1]; pz = s6[2];
            }
            pxs[slot] = px; pys[slot] = py; pzs[slot] = pz;
            sps[slot] = px*px + py*py + pz*pz;
        }
    }
    __syncthreads();

    // per-thread fragment-row coords (scalar): rows = wbase + mt*16 + g + 8r
    float cxr[MT][2], cyr[MT][2], czr[MT][2], csr[MT][2];
#pragma unroll
    for (int mt = 0; mt < MT; mt++)
#pragma unroll
        for (int r = 0; r < 2; r++) {
            int m = wbase + mt * 16 + g + 8 * r;
            cxr[mt][r] = pxs[m]; cyr[mt][r] = pys[m];
            czr[mt][r] = pzs[m]; csr[mt][r] = sps[m];
        }

    float acc[MT][2][4];
#pragma unroll
    for (int mt = 0; mt < MT; mt++)
#pragma unroll
        for (int nt = 0; nt < 2; nt++)
#pragma unroll
            for (int q = 0; q < 4; q++) acc[mt][nt][q] = 0.0f;

#pragma unroll 2
    for (int k8 = 0; k8 < 16; k8++) {
        float4 pb = sP4[k8*32 + g*4 + tg];          // conflict-free LDS.128
        float4 A0 = sA4[k8*12 + 0 + tg];
        float4 A1 = sA4[k8*12 + 4 + tg];
        float4 A2 = sA4[k8*12 + 8 + tg];
        // A0 = {ex_l, ex_h, ey_l, ey_h}; A1 = {ez_l, ez_h, a_l, a_h}; A2 = {f_l, f_h, -, -}

#pragma unroll
        for (int mt = 0; mt < MT; mt++) {
            float al0 = fmaf(A1.z, csr[mt][0], fmaf(A0.x, cxr[mt][0],
                        fmaf(A0.z, cyr[mt][0], fmaf(A1.x, czr[mt][0], A2.x))));
            float ah0 = fmaf(A1.w, csr[mt][0], fmaf(A0.y, cxr[mt][0],
                        fmaf(A0.w, cyr[mt][0], fmaf(A1.y, czr[mt][0], A2.y))));
            float al1 = fmaf(A1.z, csr[mt][1], fmaf(A0.x, cxr[mt][1],
                        fmaf(A0.z, cyr[mt][1], fmaf(A1.x, czr[mt][1], A2.x))));
            float ah1 = fmaf(A1.w, csr[mt][1], fmaf(A0.y, cxr[mt][1],
                        fmaf(A0.w, cyr[mt][1], fmaf(A1.y, czr[mt][1], A2.y))));
            float w00 = ex2f(al0);   // A[row g   ][k=tg]
            float w10 = ex2f(al1);   // A[row g+8 ][k=tg]
            float w01 = ex2f(ah0);   // A[row g   ][k=tg+4]
            float w11 = ex2f(ah1);   // A[row g+8 ][k=tg+4]
            mma_tf32(acc[mt][0], w00, w10, w01, w11, pb.x, pb.y);
            mma_tf32(acc[mt][1], w00, w10, w01, w11, pb.z, pb.w);
        }
    }
    __syncthreads();   // params dead; smem_u becomes Cst

    // ---- stage C (rows = points, cols 0..15, stride 17) ----
#pragma unroll
    for (int mt = 0; mt < MT; mt++) {
        int row = wbase + mt * 16 + g;
#pragma unroll
        for (int nt = 0; nt < 2; nt++) {
            int col = nt * 8 + tg * 2;
            Cst[ row      * 17 + col    ] = acc[mt][nt][0];
            Cst[ row      * 17 + col + 1] = acc[mt][nt][1];
            Cst[(row + 8) * 17 + col    ] = acc[mt][nt][2];
            Cst[(row + 8) * 17 + col + 1] = acc[mt][nt][3];
        }
    }
    __syncthreads();

    // ---- epilogue: 2 points per thread ----
    const float* M  = w2g + bt * 16;
    const float* gg = grid + (size_t)bt * GD * GD * GD;
    const float dm  = (float)(GD - 1);

    float val = 0.0f;
#pragma unroll
    for (int t = 0; t < 2; t++) {
        int slot = tid + t * TPB;
        if (base + slot >= NN) continue;
        const float* o = &Cst[slot * 17];
        float px = pxs[slot], py = pys[slot], pz = pzs[slot];
        float inv = 1.0f / o[12];
        float bx = (o[0]*px + o[1]*py + o[2]*pz + o[ 9]) * inv;
        float by = (o[3]*px + o[4]*py + o[5]*pz + o[10]) * inv;
        float bz = (o[6]*px + o[7]*py + o[8]*pz + o[11]) * inv;

        float gx = M[0]*bx + M[1]*by + M[2]*bz  + M[3];
        float gy = M[4]*bx + M[5]*by + M[6]*bz  + M[7];
        float gz = M[8]*bx + M[9]*by + M[10]*bz + M[11];

        float nx = 2.0f * (gx / dm) - 1.0f;
        float ny = 2.0f * (gy / dm) - 1.0f;
        float nz = 2.0f * (gz / dm) - 1.0f;

        float x = fminf(fmaxf((nx + 1.0f) * 0.5f * dm, 0.0f), dm);
        float y = fminf(fmaxf((ny + 1.0f) * 0.5f * dm, 0.0f), dm);
        float z = fminf(fmaxf((nz + 1.0f) * 0.5f * dm, 0.0f), dm);

        float x0f = floorf(x), y0f = floorf(y), z0f = floorf(z);
        float fx = x - x0f, fy = y - y0f, fz = z - z0f;
        int x0 = (int)x0f, y0 = (int)y0f, z0 = (int)z0f;
        int x1 = min(x0 + 1, GD - 1);
        int y1 = min(y0 + 1, GD - 1);
        int z1 = min(z0 + 1, GD - 1);

        int zy00 = (z0 * GD + y0) * GD;
        int zy01 = (z0 * GD + y1) * GD;
        int zy10 = (z1 * GD + y0) * GD;
        int zy11 = (z1 * GD + y1) * GD;
        float c000 = __ldg(gg + zy00 + x0);
        float c001 = __ldg(gg + zy00 + x1);
        float c010 = __ldg(gg + zy01 + x0);
        float c011 = __ldg(gg + zy01 + x1);
        float c100 = __ldg(gg + zy10 + x0);
        float c101 = __ldg(gg + zy10 + x1);
        float c110 = __ldg(gg + zy11 + x0);
        float c111 = __ldg(gg + zy11 + x1);

        float c00 = c000 + (c001 - c000) * fx;
        float c01 = c010 + (c011 - c010) * fx;
        float c10 = c100 + (c101 - c100) * fx;
        float c11 = c110 + (c111 - c110) * fx;
        float c0  = c00 + (c01 - c00) * fy;
        float c1  = c10 + (c11 - c10) * fy;
        float sdf = c0 + (c1 - c0) * fz;
        val += sdf * sdf;
    }

    // ---- deterministic block reduction ----
    red[tid] = val;
    __syncthreads();
#pragma unroll
    for (int s = TPB / 2; s > 0; s >>= 1) {
        if (tid < s) red[tid] += red[tid + s];
        __syncthreads();
    }
    if (tid == 0) {
        g_partial[blockIdx.x] = red[0];
        __threadfence();
        unsigned int t = atomicAdd(&g_count, 1u);
        s_last = (t == TOTAL_BLK - 1);
    }
    __syncthreads();

    if (s_last) {
        float s = 0.0f;
        for (int i = tid; i < TOTAL_BLK; i += TPB) s += g_partial[i];
        red[tid] = s;
        __syncthreads();
#pragma unroll
        for (int st = TPB / 2; st > 0; st >>= 1) {
            if (tid < st) red[tid] += red[tid + st];
            __syncthreads();
        }
        if (tid == 0) {
            out[0] = red[0] * (1.0f / (float)NN);
            g_count = 0;
        }
    }
}

extern "C" void kernel_launch(void* const* d_in, const int* in_sizes, int n_in,
                              void* d_out, int out_size) {
    const float* constants = (const float*)d_in[0];   // (B,K)
    const float* scales    = (const float*)d_in[1];   // (B,K)
    const float* rotations = (const float*)d_in[2];   // (B,K,3,3)
    const float* centers   = (const float*)d_in[3];   // (B,K,3)
    const float* samples   = (const float*)d_in[4];   // (B,N,6)
    const float* grid      = (const float*)d_in[5];   // (B,GD,GD,GD)
    const float* w2g       = (const float*)d_in[6];   // (B,4,4)
    float* out = (float*)d_out;

    precompute_kernel<<<2, 256>>>(constants, scales, rotations, centers);
    fused_kernel<<<TOTAL_BLK, TPB>>>(samples, grid, w2g, out);
}

// round 16
// speedup vs baseline: 1.4729x; 1.4729x over previous
#include <cuda_runtime.h>
#include <math.h>
#include <stdint.h>

#define BB 4
#define NN 50000
#define KK 128
#define GD 128
#define TPB 64
#define NWARP 2
#define PPC 128                    // points per CTA: 2 warps x 4 mtiles x 16
#define NBLK 391                   // 391*128 = 50048 >= 50000
#define TOTAL_BLK (BB * NBLK)      // 1564  (~10.6 CTAs/SM, fine-grained balance)
#define MT 4                       // m-tiles per warp

// g_P4: B operand, float4 {P[n=g][k], P[n=g][k+4], P[n=g+8][k], P[n=g+8][k+4]}
//   laid out [b][k8(16)][g(8)][tg(4)]  (k = k8*8 + tg)
//   n: 0-8 = Rrel row-major, 9-11 = u (= ct - Rrel*c), 12 = 1, 13-15 = 0
// g_A4: exp-arg params [b][k8(16)][j(3)][tg(4)] float4:
//   j0 = {ex_k, ex_k+4, ey_k, ey_k+4}, j1 = {ez_k, ez_k+4, a_k, a_k+4}, j2 = {f_k, f_k+4, 0, 0}
__device__ float4 g_P4[BB * 16 * 8 * 4];
__device__ float4 g_A4[BB * 16 * 3 * 4];

__device__ float        g_partial[TOTAL_BLK];
__device__ unsigned int g_count = 0;

__device__ __forceinline__ float ex2f(float x) {
    float y; asm("ex2.approx.ftz.f32 %0, %1;" : "=f"(y) : "f"(x)); return y;
}
__device__ __forceinline__ float tf32r(float x) {
    float y; asm("cvt.rna.tf32.f32 %0, %1;" : "=f"(y) : "f"(x)); return y;
}

__device__ __forceinline__ void mma_tf32(float* c, float a0, float a1,
                                         float a2, float a3,
                                         float b0, float b1) {
    asm("mma.sync.aligned.m16n8k8.row.col.f32.tf32.tf32.f32 "
        "{%0,%1,%2,%3}, {%4,%5,%6,%7}, {%8,%9}, {%0,%1,%2,%3};"
        : "+f"(c[0]), "+f"(c[1]), "+f"(c[2]), "+f"(c[3])
        : "r"(__float_as_uint(a0)), "r"(__float_as_uint(a1)),
          "r"(__float_as_uint(a2)), "r"(__float_as_uint(a3)),
          "r"(__float_as_uint(b0)), "r"(__float_as_uint(b1)));
}

__global__ void precompute_kernel(const float* __restrict__ constants,
                                  const float* __restrict__ scales,
                                  const float* __restrict__ rot,
                                  const float* __restrict__ centers) {
    int idx = blockIdx.x * blockDim.x + threadIdx.x;
    if (idx >= BB * KK) return;
    int b = idx / KK;
    int k = idx - b * KK;
    int bt = (b + 1) & 3;

    const float* R  = rot + (size_t)(b  * KK + k) * 9;
    const float* Rt = rot + (size_t)(bt * KK + k) * 9;
    float Rr[9];
#pragma unroll
    for (int i = 0; i < 3; i++)
#pragma unroll
        for (int l = 0; l < 3; l++)
            Rr[i*3+l] = Rt[i*3+0]*R[l*3+0] + Rt[i*3+1]*R[l*3+1] + Rt[i*3+2]*R[l*3+2];
    const float* c  = centers + (size_t)(b  * KK + k) * 3;
    const float* ct = centers + (size_t)(bt * KK + k) * 3;
    float cx = c[0], cy = c[1], cz = c[2];
    float s  = scales[b * KK + k];
    float cc = constants[b * KK + k];
    float a  = -1.4426950408889634f / (2.0f * s * s);
    float lb = log2f(cc * cc);

    int k8 = k >> 3, j = k & 7, tg = j & 3, half = j >> 2;

    float v[16];
#pragma unroll
    for (int n = 0; n < 9; n++) v[n] = tf32r(Rr[n]);
    v[ 9] = tf32r(ct[0] - (Rr[0]*cx + Rr[1]*cy + Rr[2]*cz));
    v[10] = tf32r(ct[1] - (Rr[3]*cx + Rr[4]*cy + Rr[5]*cz));
    v[11] = tf32r(ct[2] - (Rr[6]*cx + Rr[7]*cy + Rr[8]*cz));
    v[12] = 1.0f; v[13] = 0.0f; v[14] = 0.0f; v[15] = 0.0f;

    float* P4 = (float*)g_P4;
#pragma unroll
    for (int n = 0; n < 16; n++) {
        int g8 = n & 7, hi = n >> 3;
        P4[((((b*16 + k8)*8 + g8)*4 + tg) << 2) + hi*2 + half] = v[n];
    }

    float* A4 = (float*)g_A4;
    float ex = -2.0f * a * cx;
    float ey = -2.0f * a * cy;
    float ez = -2.0f * a * cz;
    float ff = a * (cx*cx + cy*cy + cz*cz) + lb;
    int abase = ((b*16 + k8)*3) * 16 + tg * 4;
    A4[abase +  0 + half]     = ex;
    A4[abase +  0 + 2 + half] = ey;
    A4[abase + 16 + half]     = ez;
    A4[abase + 16 + 2 + half] = a;
    A4[abase + 32 + half]     = ff;
    // comps 2,3 of j2 stay zero-initialized
}

#define PARAM_BYTES (8192 + 3072)          // sP4 + sA4
#define CST_BYTES   (PPC * 17 * 4)         // 8704
#define UNION_BYTES (PARAM_BYTES)          // 11264 > 8704

__global__ __launch_bounds__(TPB, 10)
void fused_kernel(const float* __restrict__ samples,
                  const float* __restrict__ grid,
                  const float* __restrict__ w2g,
                  float* __restrict__ out) {
    int b   = blockIdx.x / NBLK;
    int blk = blockIdx.x - b * NBLK;
    int bt  = (b + 1) & 3;
    int base = blk * PPC;

    // union: [mainloop] sP4 (8KB) + sA4 (3KB)  /  [epilogue] Cst (8.5KB)
    __shared__ __align__(16) char smem_u[UNION_BYTES];
    __shared__ float  pxs[PPC], pys[PPC], pzs[PPC], sps[PPC];  // 2 KB
    __shared__ float  red[TPB];
    __shared__ bool   s_last;

    float4* sP4 = (float4*)smem_u;               // 512 float4
    float4* sA4 = (float4*)(smem_u + 8192);      // 192 float4
    float*  Cst = (float*)smem_u;                // PPC*17 floats (after sync)

    int tid  = threadIdx.x;
    int lane = tid & 31, warp = tid >> 5;
    int g    = lane >> 2, tg = lane & 3;
    int wbase = warp * 64;

    // ---- stage params + points ----
    {
        const float4* Pg = g_P4 + (size_t)b * 512;
        for (int i = tid; i < 512; i += TPB) sP4[i] = Pg[i];
        const float4* Ag = g_A4 + (size_t)b * 192;
        for (int i = tid; i < 192; i += TPB) sA4[i] = Ag[i];

#pragma unroll
        for (int t = 0; t < 2; t++) {
            int slot = tid + t * TPB;
            int gi = base + slot;
            float px = 0.f, py = 0.f, pz = 0.f;
            if (gi < NN) {
                const float* s6 = samples + (size_t)(b * NN + gi) * 6;
                px = s6[0]; py = s6[1]; pz = s6[2];
            }
            pxs[slot] = px; pys[slot] = py; pzs[slot] = pz;
            sps[slot] = px*px + py*py + pz*pz;
        }
    }
    __syncthreads();

    // per-thread fragment-row coords (scalar): rows = wbase + mt*16 + g + 8r
    float cxr[MT][2], cyr[MT][2], czr[MT][2], csr[MT][2];
#pragma unroll
    for (int mt = 0; mt < MT; mt++)
#pragma unroll
        for (int r = 0; r < 2; r++) {
            int m = wbase + mt * 16 + g + 8 * r;
            cxr[mt][r] = pxs[m]; cyr[mt][r] = pys[m];
            czr[mt][r] = pzs[m]; csr[mt][r] = sps[m];
        }

    float acc[MT][2][4];
#pragma unroll
    for (int mt = 0; mt < MT; mt++)
#pragma unroll
        for (int nt = 0; nt < 2; nt++)
#pragma unroll
            for (int q = 0; q < 4; q++) acc[mt][nt][q] = 0.0f;

#pragma unroll 2
    for (int k8 = 0; k8 < 16; k8++) {
        float4 pb = sP4[k8*32 + g*4 + tg];          // conflict-free LDS.128
        float4 A0 = sA4[k8*12 + 0 + tg];
        float4 A1 = sA4[k8*12 + 4 + tg];
        float4 A2 = sA4[k8*12 + 8 + tg];
        // A0 = {ex_l, ex_h, ey_l, ey_h}; A1 = {ez_l, ez_h, a_l, a_h}; A2 = {f_l, f_h, -, -}

#pragma unroll
        for (int mt = 0; mt < MT; mt++) {
            float al0 = fmaf(A1.z, csr[mt][0], fmaf(A0.x, cxr[mt][0],
                        fmaf(A0.z, cyr[mt][0], fmaf(A1.x, czr[mt][0], A2.x))));
            float ah0 = fmaf(A1.w, csr[mt][0], fmaf(A0.y, cxr[mt][0],
                        fmaf(A0.w, cyr[mt][0], fmaf(A1.y, czr[mt][0], A2.y))));
            float al1 = fmaf(A1.z, csr[mt][1], fmaf(A0.x, cxr[mt][1],
                        fmaf(A0.z, cyr[mt][1], fmaf(A1.x, czr[mt][1], A2.x))));
            float ah1 = fmaf(A1.w, csr[mt][1], fmaf(A0.y, cxr[mt][1],
                        fmaf(A0.w, cyr[mt][1], fmaf(A1.y, czr[mt][1], A2.y))));
            float w00 = ex2f(al0);   // A[row g   ][k=tg]
            float w10 = ex2f(al1);   // A[row g+8 ][k=tg]
            float w01 = ex2f(ah0);   // A[row g   ][k=tg+4]
            float w11 = ex2f(ah1);   // A[row g+8 ][k=tg+4]
            mma_tf32(acc[mt][0], w00, w10, w01, w11, pb.x, pb.y);
            mma_tf32(acc[mt][1], w00, w10, w01, w11, pb.z, pb.w);
        }
    }
    __syncthreads();   // params dead; smem_u becomes Cst

    // ---- stage C (rows = points, cols 0..15, stride 17) ----
#pragma unroll
    for (int mt = 0; mt < MT; mt++) {
        int row = wbase + mt * 16 + g;
#pragma unroll
        for (int nt = 0; nt < 2; nt++) {
            int col = nt * 8 + tg * 2;
            Cst[ row      * 17 + col    ] = acc[mt][nt][0];
            Cst[ row      * 17 + col + 1] = acc[mt][nt][1];
            Cst[(row + 8) * 17 + col    ] = acc[mt][nt][2];
            Cst[(row + 8) * 17 + col + 1] = acc[mt][nt][3];
        }
    }
    __syncthreads();

    // ---- epilogue: 2 points per thread ----
    const float* M  = w2g + bt * 16;
    const float* gg = grid + (size_t)bt * GD * GD * GD;
    const float dm  = (float)(GD - 1);

    float val = 0.0f;
#pragma unroll
    for (int t = 0; t < 2; t++) {
        int slot = tid + t * TPB;
        if (base + slot >= NN) continue;
        const float* o = &Cst[slot * 17];
        float px = pxs[slot], py = pys[slot], pz = pzs[slot];
        float inv = 1.0f / o[12];
        float bx = (o[0]*px + o[1]*py + o[2]*pz + o[ 9]) * inv;
        float by = (o[3]*px + o[4]*py + o[5]*pz + o[10]) * inv;
        float bz = (o[6]*px + o[7]*py + o[8]*pz + o[11]) * inv;

        float gx = M[0]*bx + M[1]*by + M[2]*bz  + M[3];
        float gy = M[4]*bx + M[5]*by + M[6]*bz  + M[7];
        float gz = M[8]*bx + M[9]*by + M[10]*bz + M[11];

        float nx = 2.0f * (gx / dm) - 1.0f;
        float ny = 2.0f * (gy / dm) - 1.0f;
        float nz = 2.0f * (gz / dm) - 1.0f;

        float x = fminf(fmaxf((nx + 1.0f) * 0.5f * dm, 0.0f), dm);
        float y = fminf(fmaxf((ny + 1.0f) * 0.5f * dm, 0.0f), dm);
        float z = fminf(fmaxf((nz + 1.0f) * 0.5f * dm, 0.0f), dm);

        float x0f = floorf(x), y0f = floorf(y), z0f = floorf(z);
        float fx = x - x0f, fy = y - y0f, fz = z - z0f;
        int x0 = (int)x0f, y0 = (int)y0f, z0 = (int)z0f;
        int x1 = min(x0 + 1, GD - 1);
        int y1 = min(y0 + 1, GD - 1);
        int z1 = min(z0 + 1, GD - 1);

        int zy00 = (z0 * GD + y0) * GD;
        int zy01 = (z0 * GD + y1) * GD;
        int zy10 = (z1 * GD + y0) * GD;
        int zy11 = (z1 * GD + y1) * GD;
        float c000 = __ldg(gg + zy00 + x0);
        float c001 = __ldg(gg + zy00 + x1);
        float c010 = __ldg(gg + zy01 + x0);
        float c011 = __ldg(gg + zy01 + x1);
        float c100 = __ldg(gg + zy10 + x0);
        float c101 = __ldg(gg + zy10 + x1);
        float c110 = __ldg(gg + zy11 + x0);
        float c111 = __ldg(gg + zy11 + x1);

        float c00 = c000 + (c001 - c000) * fx;
        float c01 = c010 + (c011 - c010) * fx;
        float c10 = c100 + (c101 - c100) * fx;
        float c11 = c110 + (c111 - c110) * fx;
        float c0  = c00 + (c01 - c00) * fy;
        float c1  = c10 + (c11 - c10) * fy;
        float sdf = c0 + (c1 - c0) * fz;
        val += sdf * sdf;
    }

    // ---- deterministic block reduction ----
    red[tid] = val;
    __syncthreads();
#pragma unroll
    for (int s = TPB / 2; s > 0; s >>= 1) {
        if (tid < s) red[tid] += red[tid + s];
        __syncthreads();
    }
    if (tid == 0) {
        g_partial[blockIdx.x] = red[0];
        __threadfence();
        unsigned int t = atomicAdd(&g_count, 1u);
        s_last = (t == TOTAL_BLK - 1);
    }
    __syncthreads();

    if (s_last) {
        float s = 0.0f;
        for (int i = tid; i < TOTAL_BLK; i += TPB) s += g_partial[i];
        red[tid] = s;
        __syncthreads();
#pragma unroll
        for (int st = TPB / 2; st > 0; st >>= 1) {
            if (tid < st) red[tid] += red[tid + st];
            __syncthreads();
        }
        if (tid == 0) {
            out[0] = red[0] * (1.0f / (float)NN);
            g_count = 0;
        }
    }
}

extern "C" void kernel_launch(void* const* d_in, const int* in_sizes, int n_in,
                              void* d_out, int out_size) {
    const float* constants = (const float*)d_in[0];   // (B,K)
    const float* scales    = (const float*)d_in[1];   // (B,K)
    const float* rotations = (const float*)d_in[2];   // (B,K,3,3)
    const float* centers   = (const float*)d_in[3];   // (B,K,3)
    const float* samples   = (const float*)d_in[4];   // (B,N,6)
    const float* grid      = (const float*)d_in[5];   // (B,GD,GD,GD)
    const float* w2g       = (const float*)d_in[6];   // (B,4,4)
    float* out = (float*)d_out;

    precompute_kernel<<<2, 256>>>(constants, scales, rotations, centers);
    fused_kernel<<<TOTAL_BLK, TPB>>>(samples, grid, w2g, out);
}

// round 17
// speedup vs baseline: 1.4923x; 1.0132x over previous
#include <cuda_runtime.h>
#include <math.h>
#include <stdint.h>

#define BB 4
#define NN 50000
#define KK 128
#define GD 128
#define TPB 64
#define PPC 64                     // points per CTA: 2 warps x 2 mtiles x 16
#define NBLK 782                   // 782*64 = 50048 >= 50000
#define TOTAL_BLK (BB * NBLK)      // 3128
#define MT 2                       // m-tiles per warp

// g_P4: B operand, float4 {P[n=g][k], P[n=g][k+4], P[n=g+8][k], P[n=g+8][k+4]}
//   laid out [b][k8(16)][g(8)][tg(4)]  (k = k8*8 + tg)
//   n: 0-8 = Rrel row-major, 9-11 = u (= ct - Rrel*c), 12 = 1, 13-15 = 0
// g_A4: exp-arg params [b][k8(16)][j(3)][tg(4)] float4:
//   j0 = {ex_k, ex_k+4, ey_k, ey_k+4}, j1 = {ez_k, ez_k+4, a_k, a_k+4}, j2 = {f_k, f_k+4, 0, 0}
__device__ float4 g_P4[BB * 16 * 8 * 4];
__device__ float4 g_A4[BB * 16 * 3 * 4];

__device__ float        g_partial[TOTAL_BLK];
__device__ unsigned int g_count = 0;

__device__ __forceinline__ float ex2f(float x) {
    float y; asm("ex2.approx.ftz.f32 %0, %1;" : "=f"(y) : "f"(x)); return y;
}
__device__ __forceinline__ float tf32r(float x) {
    float y; asm("cvt.rna.tf32.f32 %0, %1;" : "=f"(y) : "f"(x)); return y;
}

__device__ __forceinline__ void mma_tf32(float* c, float a0, float a1,
                                         float a2, float a3,
                                         float b0, float b1) {
    asm("mma.sync.aligned.m16n8k8.row.col.f32.tf32.tf32.f32 "
        "{%0,%1,%2,%3}, {%4,%5,%6,%7}, {%8,%9}, {%0,%1,%2,%3};"
        : "+f"(c[0]), "+f"(c[1]), "+f"(c[2]), "+f"(c[3])
        : "r"(__float_as_uint(a0)), "r"(__float_as_uint(a1)),
          "r"(__float_as_uint(a2)), "r"(__float_as_uint(a3)),
          "r"(__float_as_uint(b0)), "r"(__float_as_uint(b1)));
}

__global__ void precompute_kernel(const float* __restrict__ constants,
                                  const float* __restrict__ scales,
                                  const float* __restrict__ rot,
                                  const float* __restrict__ centers) {
    int idx = blockIdx.x * blockDim.x + threadIdx.x;
    if (idx >= BB * KK) return;
    int b = idx / KK;
    int k = idx - b * KK;
    int bt = (b + 1) & 3;

    const float* R  = rot + (size_t)(b  * KK + k) * 9;
    const float* Rt = rot + (size_t)(bt * KK + k) * 9;
    float Rr[9];
#pragma unroll
    for (int i = 0; i < 3; i++)
#pragma unroll
        for (int l = 0; l < 3; l++)
            Rr[i*3+l] = Rt[i*3+0]*R[l*3+0] + Rt[i*3+1]*R[l*3+1] + Rt[i*3+2]*R[l*3+2];
    const float* c  = centers + (size_t)(b  * KK + k) * 3;
    const float* ct = centers + (size_t)(bt * KK + k) * 3;
    float cx = c[0], cy = c[1], cz = c[2];
    float s  = scales[b * KK + k];
    float cc = constants[b * KK + k];
    float a  = -1.4426950408889634f / (2.0f * s * s);
    float lb = log2f(cc * cc);

    int k8 = k >> 3, j = k & 7, tg = j & 3, half = j >> 2;

    float v[16];
#pragma unroll
    for (int n = 0; n < 9; n++) v[n] = tf32r(Rr[n]);
    v[ 9] = tf32r(ct[0] - (Rr[0]*cx + Rr[1]*cy + Rr[2]*cz));
    v[10] = tf32r(ct[1] - (Rr[3]*cx + Rr[4]*cy + Rr[5]*cz));
    v[11] = tf32r(ct[2] - (Rr[6]*cx + Rr[7]*cy + Rr[8]*cz));
    v[12] = 1.0f; v[13] = 0.0f; v[14] = 0.0f; v[15] = 0.0f;

    float* P4 = (float*)g_P4;
#pragma unroll
    for (int n = 0; n < 16; n++) {
        int g8 = n & 7, hi = n >> 3;
        P4[((((b*16 + k8)*8 + g8)*4 + tg) << 2) + hi*2 + half] = v[n];
    }

    float* A4 = (float*)g_A4;
    float ex = -2.0f * a * cx;
    float ey = -2.0f * a * cy;
    float ez = -2.0f * a * cz;
    float ff = a * (cx*cx + cy*cy + cz*cz) + lb;
    int abase = ((b*16 + k8)*3) * 16 + tg * 4;
    A4[abase +  0 + half]     = ex;
    A4[abase +  0 + 2 + half] = ey;
    A4[abase + 16 + half]     = ez;
    A4[abase + 16 + 2 + half] = a;
    A4[abase + 32 + half]     = ff;
    // comps 2,3 of j2 stay zero-initialized
}

#define PARAM_BYTES (8192 + 3072)          // sP4 + sA4
#define UNION_BYTES (PARAM_BYTES)          // 11264 > Cst (64*17*4 = 4352)

__global__ __launch_bounds__(TPB, 13)
void fused_kernel(const float* __restrict__ samples,
                  const float* __restrict__ grid,
                  const float* __restrict__ w2g,
                  float* __restrict__ out) {
    int b   = blockIdx.x / NBLK;
    int blk = blockIdx.x - b * NBLK;
    int bt  = (b + 1) & 3;
    int base = blk * PPC;

    // union: [mainloop] sP4 (8KB) + sA4 (3KB)  /  [epilogue] Cst (4.3KB)
    __shared__ __align__(16) char smem_u[UNION_BYTES];
    __shared__ float  pxs[PPC], pys[PPC], pzs[PPC], sps[PPC];  // 1 KB
    __shared__ float  red[TPB];
    __shared__ bool   s_last;

    float4* sP4 = (float4*)smem_u;               // 512 float4
    float4* sA4 = (float4*)(smem_u + 8192);      // 192 float4
    float*  Cst = (float*)smem_u;                // PPC*17 floats (after sync)

    int tid  = threadIdx.x;
    int lane = tid & 31, warp = tid >> 5;
    int g    = lane >> 2, tg = lane & 3;
    int wbase = warp * 32;

    // ---- stage params + points ----
    {
        const float4* Pg = g_P4 + (size_t)b * 512;
        for (int i = tid; i < 512; i += TPB) sP4[i] = Pg[i];
        const float4* Ag = g_A4 + (size_t)b * 192;
        for (int i = tid; i < 192; i += TPB) sA4[i] = Ag[i];

        int gi = base + tid;
        float px = 0.f, py = 0.f, pz = 0.f;
        if (gi < NN) {
            const float* s6 = samples + (size_t)(b * NN + gi) * 6;
            px = s6[0]; py = s6[1]; pz = s6[2];
        }
        pxs[tid] = px; pys[tid] = py; pzs[tid] = pz;
        sps[tid] = px*px + py*py + pz*pz;
    }
    __syncthreads();

    // per-thread fragment-row coords (scalar): rows = wbase + mt*16 + g + 8r
    float cxr[MT][2], cyr[MT][2], czr[MT][2], csr[MT][2];
#pragma unroll
    for (int mt = 0; mt < MT; mt++)
#pragma unroll
        for (int r = 0; r < 2; r++) {
            int m = wbase + mt * 16 + g + 8 * r;
            cxr[mt][r] = pxs[m]; cyr[mt][r] = pys[m];
            czr[mt][r] = pzs[m]; csr[mt][r] = sps[m];
        }

    float acc[MT][2][4];
#pragma unroll
    for (int mt = 0; mt < MT; mt++)
#pragma unroll
        for (int nt = 0; nt < 2; nt++)
#pragma unroll
            for (int q = 0; q < 4; q++) acc[mt][nt][q] = 0.0f;

#pragma unroll 4
    for (int k8 = 0; k8 < 16; k8++) {
        float4 pb = sP4[k8*32 + g*4 + tg];          // conflict-free LDS.128
        float4 A0 = sA4[k8*12 + 0 + tg];
        float4 A1 = sA4[k8*12 + 4 + tg];
        float4 A2 = sA4[k8*12 + 8 + tg];
        // A0 = {ex_l, ex_h, ey_l, ey_h}; A1 = {ez_l, ez_h, a_l, a_h}; A2 = {f_l, f_h, -, -}

#pragma unroll
        for (int mt = 0; mt < MT; mt++) {
            float al0 = fmaf(A1.z, csr[mt][0], fmaf(A0.x, cxr[mt][0],
                        fmaf(A0.z, cyr[mt][0], fmaf(A1.x, czr[mt][0], A2.x))));
            float ah0 = fmaf(A1.w, csr[mt][0], fmaf(A0.y, cxr[mt][0],
                        fmaf(A0.w, cyr[mt][0], fmaf(A1.y, czr[mt][0], A2.y))));
            float al1 = fmaf(A1.z, csr[mt][1], fmaf(A0.x, cxr[mt][1],
                        fmaf(A0.z, cyr[mt][1], fmaf(A1.x, czr[mt][1], A2.x))));
            float ah1 = fmaf(A1.w, csr[mt][1], fmaf(A0.y, cxr[mt][1],
                        fmaf(A0.w, cyr[mt][1], fmaf(A1.y, czr[mt][1], A2.y))));
            float w00 = ex2f(al0);   // A[row g   ][k=tg]
            float w10 = ex2f(al1);   // A[row g+8 ][k=tg]
            float w01 = ex2f(ah0);   // A[row g   ][k=tg+4]
            float w11 = ex2f(ah1);   // A[row g+8 ][k=tg+4]
            mma_tf32(acc[mt][0], w00, w10, w01, w11, pb.x, pb.y);
            mma_tf32(acc[mt][1], w00, w10, w01, w11, pb.z, pb.w);
        }
    }
    __syncthreads();   // params dead; smem_u becomes Cst

    // ---- stage C (rows = points, cols 0..15, stride 17) ----
#pragma unroll
    for (int mt = 0; mt < MT; mt++) {
        int row = wbase + mt * 16 + g;
#pragma unroll
        for (int nt = 0; nt < 2; nt++) {
            int col = nt * 8 + tg * 2;
            Cst[ row      * 17 + col    ] = acc[mt][nt][0];
            Cst[ row      * 17 + col + 1] = acc[mt][nt][1];
            Cst[(row + 8) * 17 + col    ] = acc[mt][nt][2];
            Cst[(row + 8) * 17 + col + 1] = acc[mt][nt][3];
        }
    }
    __syncthreads();

    // ---- epilogue: 1 point per thread ----
    const float* M  = w2g + bt * 16;
    const float* gg = grid + (size_t)bt * GD * GD * GD;
    const float dm  = (float)(GD - 1);

    float val = 0.0f;
    if (base + tid < NN) {
        const float* o = &Cst[tid * 17];
        float px = pxs[tid], py = pys[tid], pz = pzs[tid];
        float inv = 1.0f / o[12];
        float bx = (o[0]*px + o[1]*py + o[2]*pz + o[ 9]) * inv;
        float by = (o[3]*px + o[4]*py + o[5]*pz + o[10]) * inv;
        float bz = (o[6]*px + o[7]*py + o[8]*pz + o[11]) * inv;

        float gx = M[0]*bx + M[1]*by + M[2]*bz  + M[3];
        float gy = M[4]*bx + M[5]*by + M[6]*bz  + M[7];
        float gz = M[8]*bx + M[9]*by + M[10]*bz + M[11];

        float nx = 2.0f * (gx / dm) - 1.0f;
        float ny = 2.0f * (gy / dm) - 1.0f;
        float nz = 2.0f * (gz / dm) - 1.0f;

        float x = fminf(fmaxf((nx + 1.0f) * 0.5f * dm, 0.0f), dm);
        float y = fminf(fmaxf((ny + 1.0f) * 0.5f * dm, 0.0f), dm);
        float z = fminf(fmaxf((nz + 1.0f) * 0.5f * dm, 0.0f), dm);

        float x0f = floorf(x), y0f = floorf(y), z0f = floorf(z);
        float fx = x - x0f, fy = y - y0f, fz = z - z0f;
        int x0 = (int)x0f, y0 = (int)y0f, z0 = (int)z0f;
        int x1 = min(x0 + 1, GD - 1);
        int y1 = min(y0 + 1, GD - 1);
        int z1 = min(z0 + 1, GD - 1);

        int zy00 = (z0 * GD + y0) * GD;
        int zy01 = (z0 * GD + y1) * GD;
        int zy10 = (z1 * GD + y0) * GD;
        int zy11 = (z1 * GD + y1) * GD;
        float c000 = __ldg(gg + zy00 + x0);
        float c001 = __ldg(gg + zy00 + x1);
        float c010 = __ldg(gg + zy01 + x0);
        float c011 = __ldg(gg + zy01 + x1);
        float c100 = __ldg(gg + zy10 + x0);
        float c101 = __ldg(gg + zy10 + x1);
        float c110 = __ldg(gg + zy11 + x0);
        float c111 = __ldg(gg + zy11 + x1);

        float c00 = c000 + (c001 - c000) * fx;
        float c01 = c010 + (c011 - c010) * fx;
        float c10 = c100 + (c101 - c100) * fx;
        float c11 = c110 + (c111 - c110) * fx;
        float c0  = c00 + (c01 - c00) * fy;
        float c1  = c10 + (c11 - c10) * fy;
        float sdf = c0 + (c1 - c0) * fz;
        val = sdf * sdf;
    }

    // ---- deterministic block reduction ----
    red[tid] = val;
    __syncthreads();
#pragma unroll
    for (int s = TPB / 2; s > 0; s >>= 1) {
        if (tid < s) red[tid] += red[tid + s];
        __syncthreads();
    }
    if (tid == 0) {
        g_partial[blockIdx.x] = red[0];
        __threadfence();
        unsigned int t = atomicAdd(&g_count, 1u);
        s_last = (t == TOTAL_BLK - 1);
    }
    __syncthreads();

    if (s_last) {
        float s = 0.0f;
        for (int i = tid; i < TOTAL_BLK; i += TPB) s += g_partial[i];
        red[tid] = s;
        __syncthreads();
#pragma unroll
        for (int st = TPB / 2; st > 0; st >>= 1) {
            if (tid < st) red[tid] += red[tid + st];
            __syncthreads();
        }
        if (tid == 0) {
            out[0] = red[0] * (1.0f / (float)NN);
            g_count = 0;
        }
    }
}

extern "C" void kernel_launch(void* const* d_in, const int* in_sizes, int n_in,
                              void* d_out, int out_size) {
    const float* constants = (const float*)d_in[0];   // (B,K)
    const float* scales    = (const float*)d_in[1];   // (B,K)
    const float* rotations = (const float*)d_in[2];   // (B,K,3,3)
    const float* centers   = (const float*)d_in[3];   // (B,K,3)
    const float* samples   = (const float*)d_in[4];   // (B,N,6)
    const float* grid      = (const float*)d_in[5];   // (B,GD,GD,GD)
    const float* w2g       = (const float*)d_in[6];   // (B,4,4)
    float* out = (float*)d_out;

    precompute_kernel<<<2, 256>>>(constants, scales, rotations, centers);
    fused_kernel<<<TOTAL_BLK, TPB>>>(samples, grid, w2g, out);
}